// round 14
// baseline (speedup 1.0000x reference)
#include <cuda_runtime.h>
#include <math.h>
#include <stdint.h>

#define NMAX 50000
#define EMAX 850000
#define F 128

// ---------------- scratch ----------------
__device__ float d_xn[NMAX * F];
__device__ float d_h [NMAX * F];
__device__ float d_hw[NMAX * F];
__device__ float d_simr[EMAX];         // sims, row-CSR ordered
__device__ float d_adjr[EMAX];         // base attention (exp), row-CSR ordered
__device__ float d_wcsr[EMAX];         // current edge weight, col-CSR ordered
__device__ float d_degw[NMAX];
// two CSRs: [0]=by row, [1]=by col
__device__ int   d_hist2 [2 * (NMAX + 1)];   // zero-init at load; re-zeroed by scan1 each call
__device__ int   d_start2[2 * (NMAX + 1)];
__device__ int   d_coff2 [2 * NMAX];
__device__ int   d_bsum2 [2 * 64];
__device__ int2  d_rcsr[EMAX];         // row-CSR: {col endpoint, col-CSR pos}
__device__ int   d_ccsr_src[EMAX];     // col-CSR: row endpoint

// ---------------- helpers ----------------
__device__ __forceinline__ float warpSum(float v) {
    v += __shfl_xor_sync(0xffffffffu, v, 16);
    v += __shfl_xor_sync(0xffffffffu, v, 8);
    v += __shfl_xor_sync(0xffffffffu, v, 4);
    v += __shfl_xor_sync(0xffffffffu, v, 2);
    v += __shfl_xor_sync(0xffffffffu, v, 1);
    return v;
}
__device__ __forceinline__ float warpMax(float v) {
    v = fmaxf(v, __shfl_xor_sync(0xffffffffu, v, 16));
    v = fmaxf(v, __shfl_xor_sync(0xffffffffu, v, 8));
    v = fmaxf(v, __shfl_xor_sync(0xffffffffu, v, 4));
    v = fmaxf(v, __shfl_xor_sync(0xffffffffu, v, 2));
    v = fmaxf(v, __shfl_xor_sync(0xffffffffu, v, 1));
    return v;
}
__device__ __forceinline__ float halfSum(float s) {
    s += __shfl_xor_sync(0xffffffffu, s, 8);
    s += __shfl_xor_sync(0xffffffffu, s, 4);
    s += __shfl_xor_sync(0xffffffffu, s, 2);
    s += __shfl_xor_sync(0xffffffffu, s, 1);
    return s;
}
// packed fp32x2 ops (sm_103a; ptxas never auto-fuses these)
__device__ __forceinline__ unsigned long long pack2(float x, float y) {
    unsigned long long r;
    asm("mov.b64 %0, {%1, %2};" : "=l"(r) : "f"(x), "f"(y));
    return r;
}
__device__ __forceinline__ float2 unpack2f(unsigned long long v) {
    float2 r;
    asm("mov.b64 {%0, %1}, %2;" : "=f"(r.x), "=f"(r.y) : "l"(v));
    return r;
}
__device__ __forceinline__ unsigned long long ffma2(unsigned long long a, unsigned long long b,
                                                    unsigned long long c) {
    unsigned long long d;
    asm("fma.rn.f32x2 %0, %1, %2, %3;" : "=l"(d) : "l"(a), "l"(b), "l"(c));
    return d;
}

// L2-normalize one node per warp + zero degw (layer 0 prep)
__device__ __forceinline__ void normalize_body(const float* __restrict__ X, int N, int vid) {
    int node = vid >> 5;
    if (node >= N) return;
    int lane = vid & 31;
    float4 v = ((const float4*)(X + (size_t)node * F))[lane];
    float ss = v.x * v.x + v.y * v.y + v.z * v.z + v.w * v.w;
    ss = warpSum(ss);
    float inv = 1.f / fmaxf(sqrtf(ss), 1e-12f);
    v.x *= inv; v.y *= inv; v.z *= inv; v.w *= inv;
    ((float4*)(d_xn + (size_t)node * F))[lane] = v;
    if (lane == 0) d_degw[node] = 0.f;
}

// ---------------- CSR build ----------------
__global__ void combo_hist_norm_kernel(const int* __restrict__ erow, const int* __restrict__ ecol,
                                       int E, const float* __restrict__ X, int N,
                                       int histBlocks, int Ehalf) {
    if ((int)blockIdx.x < histBlocks) {
        int e = blockIdx.x * blockDim.x + threadIdx.x;
        if (e < Ehalf) {
            atomicAdd(&d_hist2[erow[e]], 1);
            atomicAdd(&d_hist2[(NMAX + 1) + ecol[e]], 1);
        }
        int e2 = e + Ehalf;
        if (e2 < E) {
            atomicAdd(&d_hist2[erow[e2]], 1);
            atomicAdd(&d_hist2[(NMAX + 1) + ecol[e2]], 1);
        }
    } else {
        int vid = (blockIdx.x - histBlocks) * blockDim.x + threadIdx.x;
        normalize_body(X, N, vid);
    }
}
// per-1024 chunk inclusive scan; also RE-ZEROS hist after reading (invariant for next call)
__global__ void scan1_kernel(int n) {
    __shared__ int tsum[256];
    int y = blockIdx.y;
    int* hist = d_hist2 + y * (NMAX + 1);
    int* start = d_start2 + y * (NMAX + 1);
    int* bsum  = d_bsum2 + y * 64;
    int b = blockIdx.x, t = threadIdx.x;
    int base = b * 1024 + t * 4;
    int v0 = (base + 0 < n) ? hist[base + 0] : 0;
    int v1 = (base + 1 < n) ? hist[base + 1] : 0;
    int v2 = (base + 2 < n) ? hist[base + 2] : 0;
    int v3 = (base + 3 < n) ? hist[base + 3] : 0;
    if (base + 0 < n) hist[base + 0] = 0;
    if (base + 1 < n) hist[base + 1] = 0;
    if (base + 2 < n) hist[base + 2] = 0;
    if (base + 3 < n) hist[base + 3] = 0;
    int s0 = v0, s1 = s0 + v1, s2 = s1 + v2, s3 = s2 + v3;
    tsum[t] = s3;
    __syncthreads();
    for (int off = 1; off < 256; off <<= 1) {
        int x = (t >= off) ? tsum[t - off] : 0;
        __syncthreads();
        tsum[t] += x;
        __syncthreads();
    }
    int add = (t > 0) ? tsum[t - 1] : 0;
    if (base + 0 < n) start[base + 1] = s0 + add;
    if (base + 1 < n) start[base + 2] = s1 + add;
    if (base + 2 < n) start[base + 3] = s2 + add;
    if (base + 3 < n) start[base + 4] = s3 + add;
    if (t == 255) bsum[b] = tsum[255];
}
// adds cross-chunk bases; block-sums staged in smem + warp-scanned
__global__ void scan3_kernel(int n, int nblocks) {
    __shared__ int sb[64];
    int y = blockIdx.y;
    int* start = d_start2 + y * (NMAX + 1);
    int* coff  = d_coff2 + y * NMAX;
    const int* bsum = d_bsum2 + y * 64;
    int t = threadIdx.x;
    if (t < 64) sb[t] = (t < nblocks) ? bsum[t] : 0;
    __syncthreads();
    if (t < 32) {
        int a = sb[t], b = sb[t + 32];
#pragma unroll
        for (int off = 1; off < 32; off <<= 1) {
            int v = __shfl_up_sync(0xffffffffu, a, off);
            if (t >= off) a += v;
        }
        int totalA = __shfl_sync(0xffffffffu, a, 31);
#pragma unroll
        for (int off = 1; off < 32; off <<= 1) {
            int v = __shfl_up_sync(0xffffffffu, b, off);
            if (t >= off) b += v;
        }
        int exA = __shfl_up_sync(0xffffffffu, a, 1);
        int exB = __shfl_up_sync(0xffffffffu, b, 1);
        if (t == 0) { exA = 0; exB = 0; }
        sb[t] = exA;
        sb[t + 32] = exB + totalA;
    }
    __syncthreads();
    int i = blockIdx.x * blockDim.x + t;
    if (i < n) {
        int v = start[i + 1] + sb[i >> 10];
        start[i + 1] = v;
        if (i + 1 < n) coff[i + 1] = v;
        if (i == 0) { coff[0] = 0; start[0] = 0; }
    }
}
__global__ void scatter2_kernel(const int* __restrict__ erow, const int* __restrict__ ecol,
                                int E, int Ehalf) {
    int e = blockIdx.x * blockDim.x + threadIdx.x;
    if (e < Ehalf) {
        int r = erow[e], c = ecol[e];
        int pr = atomicAdd(&d_coff2[r], 1);
        int pc = atomicAdd(&d_coff2[NMAX + c], 1);
        d_rcsr[pr] = make_int2(c, pc);
        d_ccsr_src[pc] = r;
    }
    int e2 = e + Ehalf;
    if (e2 < E) {
        int r = erow[e2], c = ecol[e2];
        int pr = atomicAdd(&d_coff2[r], 1);
        int pc = atomicAdd(&d_coff2[NMAX + c], 1);
        d_rcsr[pr] = make_int2(c, pc);
        d_ccsr_src[pc] = r;
    }
}

// ---------------- per-layer kernels ----------------
// Fused sim + weight: warp per source row, half-warp per edge, 4 edges in flight (R12 best).
__global__ void simweight_kernel(const float* __restrict__ gate, int layer, int N) {
    int gid = blockIdx.x * blockDim.x + threadIdx.x;
    int r = gid >> 5;
    if (r >= N) return;
    int lane = gid & 31;
    int half = lane >> 4;
    int hl = lane & 15;
    int p0 = d_start2[r], p1 = d_start2[r + 1];
    const float4* xrp = (const float4*)(d_xn + (size_t)r * F);
    float4 xa = xrp[hl * 2];
    float4 xb = xrp[hl * 2 + 1];
    float rs = 0.f;
    int cnt = 0;
    int p = p0;
    for (; p + 3 < p1; p += 4) {
        int cA = d_rcsr[p + half].x;
        int cB = d_rcsr[p + 2 + half].x;
        const float4* cpA = (const float4*)(d_xn + (size_t)cA * F);
        const float4* cpB = (const float4*)(d_xn + (size_t)cB * F);
        float4 a0 = cpA[hl * 2], a1 = cpA[hl * 2 + 1];
        float4 b0 = cpB[hl * 2], b1 = cpB[hl * 2 + 1];
        float sA = a0.x * xa.x + a0.y * xa.y + a0.z * xa.z + a0.w * xa.w
                 + a1.x * xb.x + a1.y * xb.y + a1.z * xb.z + a1.w * xb.w;
        float sB = b0.x * xa.x + b0.y * xa.y + b0.z * xa.z + b0.w * xa.w
                 + b1.x * xb.x + b1.y * xb.y + b1.z * xb.z + b1.w * xb.w;
        sA = halfSum(sA);
        sB = halfSum(sB);
        if (cA == r || sA < 0.1f) sA = 0.f;
        if (cB == r || sB < 0.1f) sB = 0.f;
        if (hl == 0) {
            d_simr[p + half] = sA;
            d_simr[p + 2 + half] = sB;
        }
        rs += sA + sB;
        cnt += (sA > 0.f) + (sB > 0.f);
    }
    for (; p + 1 < p1; p += 2) {
        int c = d_rcsr[p + half].x;
        const float4* cp = (const float4*)(d_xn + (size_t)c * F);
        float4 a = cp[hl * 2];
        float4 b = cp[hl * 2 + 1];
        float s = a.x * xa.x + a.y * xa.y + a.z * xa.z + a.w * xa.w
                + b.x * xb.x + b.y * xb.y + b.z * xb.z + b.w * xb.w;
        s = halfSum(s);
        if (c == r || s < 0.1f) s = 0.f;
        if (hl == 0) d_simr[p + half] = s;
        rs += s;
        cnt += (s > 0.f);
    }
    if (p < p1) {
        int c = d_rcsr[p].x;
        const float4* cp = (const float4*)(d_xn + (size_t)c * F);
        float4 a = cp[hl * 2];
        float4 b = cp[hl * 2 + 1];
        float s = a.x * xa.x + a.y * xa.y + a.z * xa.z + a.w * xa.w
                + b.x * xb.x + b.y * xb.y + b.z * xb.z + b.w * xb.w;
        s = halfSum(s);
        if (c == r || s < 0.1f) s = 0.f;
        if (lane == 0) d_simr[p] = s;
        if (half == 0) { rs += s; cnt += (s > 0.f); }
    }
    rs += __shfl_xor_sync(0xffffffffu, rs, 16);
    cnt += __shfl_xor_sync(0xffffffffu, cnt, 16);
    float lamw = 1.f / ((float)cnt + 1.f);
    float g = (layer > 0) ? gate[layer - 1] : 0.f;
    for (int q = p0 + lane; q < p1; q += 32) {
        int2 dc = d_rcsr[q];
        float wraw;
        if (dc.x == r) {
            wraw = lamw;
        } else {
            float s = d_simr[q];
            wraw = (s > 0.f) ? s / rs : 0.f;
        }
        float en = __expf(wraw);   // exp applied to ALL edges (exp(0)=1 for pruned)
        float w;
        if (layer == 0) {
            d_adjr[q] = en;
            w = en;
        } else {
            w = g * d_adjr[q] + (1.f - g) * en;
        }
        d_wcsr[dc.y] = w;
        atomicAdd(&d_degw[dc.x], w);
    }
}

// f32x2 row-pair GEMM, FOUT=128: 128 rows x 64 cols per block, 128 threads (4 warps x 32 rows).
// X staged as row-pair u64 (broadcast reads), W staged as dup pairs. FMA-bound at 128 MACs/cyc/SM.
// Epilogue scales by rsqrt(degw[row]).
#define GEMM2_SMEM (2 * 64 * 128 * 8)    // Wd (64KB) + Xp (64KB) = 128KB dynamic
__global__ void __launch_bounds__(128) gemm128x2_kernel(const float* __restrict__ X,
                                                        const float* __restrict__ Wg, int N) {
    extern __shared__ unsigned long long sm[];
    unsigned long long* Wd = sm;             // [128 k][64 cols] dup pairs (w,w)
    unsigned long long* Xp = sm + 128 * 64;  // [64 rp][128 k] row pairs (rowEven_k, rowOdd_k)
    int t = threadIdx.x, w = t >> 5, lane = t & 31;
    int ct0 = blockIdx.y * 64;
    int rowBase = blockIdx.x * 128;
    // stage W dup pairs: i = k*64 + c
    for (int i = t; i < 128 * 64; i += 128) {
        int k = i >> 6, c = i & 63;
        float wv = Wg[k * 128 + ct0 + c];
        Wd[i] = pack2(wv, wv);
    }
    // stage X row pairs: i = rp*128 + k (k fastest -> coalesced row reads)
    for (int i = t; i < 64 * 128; i += 128) {
        int rp = i >> 7, k = i & 127;
        int rA = rowBase + 2 * rp, rB = rA + 1;
        float a = (rA < N) ? X[(size_t)rA * 128 + k] : 0.f;
        float b = (rB < N) ? X[(size_t)rB * 128 + k] : 0.f;
        Xp[i] = pack2(a, b);
    }
    __syncthreads();
    // warp w handles row-pairs [w*16, w*16+16), cols ct0+lane (group0) and ct0+lane+32 (group1)
    unsigned long long acc0[16], acc1[16];
#pragma unroll
    for (int i = 0; i < 16; i++) { acc0[i] = 0ull; acc1[i] = 0ull; }
    const unsigned long long* xbase = Xp + (w * 16) * 128;
#pragma unroll 2
    for (int k = 0; k < 128; k += 2) {
        unsigned long long w00 = Wd[k * 64 + lane];
        unsigned long long w01 = Wd[k * 64 + lane + 32];
        unsigned long long w10 = Wd[(k + 1) * 64 + lane];
        unsigned long long w11 = Wd[(k + 1) * 64 + lane + 32];
#pragma unroll
        for (int rp = 0; rp < 16; rp++) {
            ulonglong2 xp = *(const ulonglong2*)(xbase + rp * 128 + k);   // broadcast 16B
            acc0[rp] = ffma2(xp.x, w00, acc0[rp]);
            acc1[rp] = ffma2(xp.x, w01, acc1[rp]);
            acc0[rp] = ffma2(xp.y, w10, acc0[rp]);
            acc1[rp] = ffma2(xp.y, w11, acc1[rp]);
        }
    }
#pragma unroll
    for (int rp = 0; rp < 16; rp++) {
        int rA = rowBase + 2 * (w * 16 + rp), rB = rA + 1;
        float2 c0 = unpack2f(acc0[rp]);   // (.x rowA, .y rowB) at col ct0+lane
        float2 c1 = unpack2f(acc1[rp]);   // at col ct0+lane+32
        if (rA < N) {
            float dw = d_degw[rA];
            float sc = (dw > 0.f) ? rsqrtf(dw) : 0.f;
            d_hw[(size_t)rA * 128 + ct0 + lane]      = c0.x * sc;
            d_hw[(size_t)rA * 128 + ct0 + lane + 32] = c1.x * sc;
        }
        if (rB < N) {
            float dw = d_degw[rB];
            float sc = (dw > 0.f) ? rsqrtf(dw) : 0.f;
            d_hw[(size_t)rB * 128 + ct0 + lane]      = c0.y * sc;
            d_hw[(size_t)rB * 128 + ct0 + lane + 32] = c1.y * sc;
        }
    }
}

// layer-2 GEMM (FOUT=40), scalar (small)
template <int FOUT, int CT>
__global__ void __launch_bounds__(256) gemm_kernel(const float* __restrict__ X,
                                                   const float* __restrict__ Wg, int N) {
    __shared__ float Ws[128 * CT];
    __shared__ float Xs[8][4][128];
    int t = threadIdx.x, w = t >> 5, lane = t & 31;
    int ct0 = blockIdx.y * CT;
    for (int i = t; i < 128 * CT; i += 256) {
        int k = i / CT, c = i - k * CT;
        Ws[i] = Wg[k * FOUT + ct0 + c];
    }
    int rowBase = blockIdx.x * 32 + w * 4;
#pragma unroll
    for (int r = 0; r < 4; r++) {
        int row = rowBase + r;
        float4 v = make_float4(0.f, 0.f, 0.f, 0.f);
        if (row < N) v = ((const float4*)(X + (size_t)row * 128))[lane];
        *(float4*)&Xs[w][r][lane * 4] = v;
    }
    __syncthreads();
    const bool has1 = (lane + 32) < CT;
    float a0[4] = {0.f, 0.f, 0.f, 0.f};
    float a1[4] = {0.f, 0.f, 0.f, 0.f};
#pragma unroll 4
    for (int k0 = 0; k0 < 128; k0 += 4) {
        float4 xv[4];
#pragma unroll
        for (int r = 0; r < 4; r++) xv[r] = *(const float4*)&Xs[w][r][k0];
#pragma unroll
        for (int kk = 0; kk < 4; kk++) {
            float w0 = Ws[(k0 + kk) * CT + lane];
            float w1 = has1 ? Ws[(k0 + kk) * CT + lane + 32] : 0.f;
#pragma unroll
            for (int r = 0; r < 4; r++) {
                float xs = (kk == 0) ? xv[r].x : (kk == 1) ? xv[r].y : (kk == 2) ? xv[r].z : xv[r].w;
                a0[r] = fmaf(xs, w0, a0[r]);
                a1[r] = fmaf(xs, w1, a1[r]);
            }
        }
    }
#pragma unroll
    for (int r = 0; r < 4; r++) {
        int row = rowBase + r;
        if (row < N) {
            float dw = d_degw[row];
            float sc = (dw > 0.f) ? rsqrtf(dw) : 0.f;
            d_hw[(size_t)row * FOUT + ct0 + lane] = a0[r] * sc;
            if (has1) d_hw[(size_t)row * FOUT + ct0 + lane + 32] = a1[r] * sc;
        }
    }
}

// Fused aggregation + relu + L2-normalize + degw re-zero; 4 edges in flight (R12 best).
__global__ void gather128_norm_kernel(const float* __restrict__ bias, float* __restrict__ out, int N) {
    int gid = blockIdx.x * blockDim.x + threadIdx.x;
    int node = gid >> 5;
    if (node >= N) return;
    int lane = gid & 31;
    int p0 = d_start2[(NMAX + 1) + node], p1 = d_start2[(NMAX + 1) + node + 1];
    float dw = d_degw[node];
    float dc = (dw > 0.f) ? rsqrtf(dw) : 0.f;
    float4 acc = make_float4(0.f, 0.f, 0.f, 0.f);
    int p = p0;
    for (; p + 3 < p1; p += 4) {
        int r0 = d_ccsr_src[p],     r1 = d_ccsr_src[p + 1];
        int r2 = d_ccsr_src[p + 2], r3 = d_ccsr_src[p + 3];
        float w0 = d_wcsr[p],     w1 = d_wcsr[p + 1];
        float w2 = d_wcsr[p + 2], w3 = d_wcsr[p + 3];
        float4 h0 = ((const float4*)(d_hw + (size_t)r0 * 128))[lane];
        float4 h1 = ((const float4*)(d_hw + (size_t)r1 * 128))[lane];
        float4 h2 = ((const float4*)(d_hw + (size_t)r2 * 128))[lane];
        float4 h3 = ((const float4*)(d_hw + (size_t)r3 * 128))[lane];
        acc.x = fmaf(w0, h0.x, fmaf(w1, h1.x, fmaf(w2, h2.x, fmaf(w3, h3.x, acc.x))));
        acc.y = fmaf(w0, h0.y, fmaf(w1, h1.y, fmaf(w2, h2.y, fmaf(w3, h3.y, acc.y))));
        acc.z = fmaf(w0, h0.z, fmaf(w1, h1.z, fmaf(w2, h2.z, fmaf(w3, h3.z, acc.z))));
        acc.w = fmaf(w0, h0.w, fmaf(w1, h1.w, fmaf(w2, h2.w, fmaf(w3, h3.w, acc.w))));
    }
    for (; p < p1; p++) {
        int r0 = d_ccsr_src[p];
        float w0 = d_wcsr[p];
        float4 h0 = ((const float4*)(d_hw + (size_t)r0 * 128))[lane];
        acc.x = fmaf(w0, h0.x, acc.x);
        acc.y = fmaf(w0, h0.y, acc.y);
        acc.z = fmaf(w0, h0.z, acc.z);
        acc.w = fmaf(w0, h0.w, acc.w);
    }
    float4 bv = ((const float4*)bias)[lane];
    acc.x = fmaxf(fmaf(acc.x, dc, bv.x), 0.f);
    acc.y = fmaxf(fmaf(acc.y, dc, bv.y), 0.f);
    acc.z = fmaxf(fmaf(acc.z, dc, bv.z), 0.f);
    acc.w = fmaxf(fmaf(acc.w, dc, bv.w), 0.f);
    ((float4*)(out + (size_t)node * 128))[lane] = acc;
    float ss = acc.x * acc.x + acc.y * acc.y + acc.z * acc.z + acc.w * acc.w;
    ss = warpSum(ss);
    float inv = 1.f / fmaxf(sqrtf(ss), 1e-12f);
    float4 xv = make_float4(acc.x * inv, acc.y * inv, acc.z * inv, acc.w * inv);
    ((float4*)(d_xn + (size_t)node * F))[lane] = xv;
    if (lane == 0) d_degw[node] = 0.f;
}

// Final layer: 40-class gather + fused log_softmax (warp/node), 2 edges in flight
__global__ void gather40_lsm_kernel(const float* __restrict__ bias, float* __restrict__ out, int N) {
    int gid = blockIdx.x * blockDim.x + threadIdx.x;
    int node = gid >> 5;
    if (node >= N) return;
    int lane = gid & 31;
    int p0 = d_start2[(NMAX + 1) + node], p1 = d_start2[(NMAX + 1) + node + 1];
    float dw = d_degw[node];
    float dc = (dw > 0.f) ? rsqrtf(dw) : 0.f;
    bool has1 = lane < 8;
    float a0 = 0.f, a1 = 0.f;
    int p = p0;
    for (; p + 1 < p1; p += 2) {
        int rA = d_ccsr_src[p], rB = d_ccsr_src[p + 1];
        float wA = d_wcsr[p], wB = d_wcsr[p + 1];
        const float* hA = d_hw + (size_t)rA * 40;
        const float* hB = d_hw + (size_t)rB * 40;
        float vA0 = hA[lane], vB0 = hB[lane];
        float vA1 = has1 ? hA[lane + 32] : 0.f;
        float vB1 = has1 ? hB[lane + 32] : 0.f;
        a0 = fmaf(wA, vA0, fmaf(wB, vB0, a0));
        a1 = fmaf(wA, vA1, fmaf(wB, vB1, a1));
    }
    if (p < p1) {
        int rA = d_ccsr_src[p];
        float wA = d_wcsr[p];
        const float* hA = d_hw + (size_t)rA * 40;
        a0 = fmaf(wA, hA[lane], a0);
        if (has1) a1 = fmaf(wA, hA[lane + 32], a1);
    }
    a0 = fmaf(a0, dc, bias[lane]);
    float v1 = -INFINITY;
    if (has1) { a1 = fmaf(a1, dc, bias[lane + 32]); v1 = a1; }
    float m = warpMax(fmaxf(a0, v1));
    float s = expf(a0 - m) + (has1 ? expf(a1 - m) : 0.f);
    s = warpSum(s);
    float lse = m + logf(s);
    out[(size_t)node * 40 + lane] = a0 - lse;
    if (has1) out[(size_t)node * 40 + lane + 32] = a1 - lse;
}

// ---------------- driver ----------------
extern "C" void kernel_launch(void* const* d_in, const int* in_sizes, int n_in,
                              void* d_out, int out_size) {
    const float* x    = (const float*)d_in[0];
    const float* gate = (const float*)d_in[1];
    const float* W0   = (const float*)d_in[2];
    const float* b0   = (const float*)d_in[3];
    const float* W1   = (const float*)d_in[4];
    const float* b1   = (const float*)d_in[5];
    const float* W2   = (const float*)d_in[6];
    const float* b2   = (const float*)d_in[7];
    const int*   ei   = (const int*)d_in[8];

    int N = in_sizes[0] / F;
    int E = in_sizes[8] / 2;
    const int* erow = ei;
    const int* ecol = ei + E;
    float* out = (float*)d_out;

    void* hp_v = nullptr;
    cudaGetSymbolAddress(&hp_v, d_h);
    float* hp = (float*)hp_v;

    cudaFuncSetAttribute(gemm128x2_kernel, cudaFuncAttributeMaxDynamicSharedMemorySize, GEMM2_SMEM);

    const int TB = 256;
    int blkN  = (N + TB - 1) / TB;
    int blkWN = ((N * 32) + TB - 1) / TB;
    int nchunks = (N + 1023) / 1024;
    int Ehalf = (E + 1) / 2;
    int blkEh = (Ehalf + TB - 1) / TB;

    // ---- build both CSRs; normalize overlapped with hist ----
    combo_hist_norm_kernel<<<blkEh + blkWN, TB>>>(erow, ecol, E, x, N, blkEh, Ehalf);
    scan1_kernel<<<dim3(nchunks, 2), 256>>>(N);
    scan3_kernel<<<dim3(blkN, 2), TB>>>(N, nchunks);
    scatter2_kernel<<<blkEh, TB>>>(erow, ecol, E, Ehalf);

    dim3 ggrid2((N + 127) / 128, 2);   // f32x2 gemm: 128 rows x 64 cols per block
    dim3 ggrid40((N + 31) / 32, 1);

    // ---- layer 0 ----
    simweight_kernel<<<blkWN, TB>>>(gate, 0, N);
    gemm128x2_kernel<<<ggrid2, 128, GEMM2_SMEM>>>(x, W0, N);
    gather128_norm_kernel<<<blkWN, TB>>>(b0, hp, N);

    // ---- layer 1 ----
    simweight_kernel<<<blkWN, TB>>>(gate, 1, N);
    gemm128x2_kernel<<<ggrid2, 128, GEMM2_SMEM>>>(hp, W1, N);
    gather128_norm_kernel<<<blkWN, TB>>>(b1, hp, N);

    // ---- layer 2 ----
    simweight_kernel<<<blkWN, TB>>>(gate, 2, N);
    gemm_kernel<40, 40><<<ggrid40, 256>>>(hp, W2, N);
    gather40_lsm_kernel<<<blkWN, TB>>>(b2, out, N);
}

// round 15
// speedup vs baseline: 1.2952x; 1.2952x over previous
#include <cuda_runtime.h>
#include <math.h>
#include <stdint.h>

#define NMAX 50000
#define EMAX 850000
#define F 128

// ---------------- scratch ----------------
__device__ float d_xn[NMAX * F];
__device__ float d_h [NMAX * F];
__device__ float d_hw[NMAX * F];
__device__ float d_simr[EMAX];         // sims, row-CSR ordered
__device__ float d_adjr[EMAX];         // base attention (exp), row-CSR ordered
__device__ float d_wcsr[EMAX];         // current edge weight, col-CSR ordered
__device__ float d_degw[NMAX];
// two CSRs: [0]=by row, [1]=by col
__device__ int   d_hist2 [2 * (NMAX + 1)];   // zero-init at load; re-zeroed by scan1 each call
__device__ int   d_start2[2 * (NMAX + 1)];
__device__ int   d_coff2 [2 * NMAX];
__device__ int   d_bsum2 [2 * 64];
__device__ int2  d_rcsr[EMAX];         // row-CSR: {col endpoint, col-CSR pos}
__device__ int   d_ccsr_src[EMAX];     // col-CSR: row endpoint

// ---------------- helpers ----------------
__device__ __forceinline__ float warpSum(float v) {
    v += __shfl_xor_sync(0xffffffffu, v, 16);
    v += __shfl_xor_sync(0xffffffffu, v, 8);
    v += __shfl_xor_sync(0xffffffffu, v, 4);
    v += __shfl_xor_sync(0xffffffffu, v, 2);
    v += __shfl_xor_sync(0xffffffffu, v, 1);
    return v;
}
__device__ __forceinline__ float warpMax(float v) {
    v = fmaxf(v, __shfl_xor_sync(0xffffffffu, v, 16));
    v = fmaxf(v, __shfl_xor_sync(0xffffffffu, v, 8));
    v = fmaxf(v, __shfl_xor_sync(0xffffffffu, v, 4));
    v = fmaxf(v, __shfl_xor_sync(0xffffffffu, v, 2));
    v = fmaxf(v, __shfl_xor_sync(0xffffffffu, v, 1));
    return v;
}
__device__ __forceinline__ float halfSum(float s) {
    s += __shfl_xor_sync(0xffffffffu, s, 8);
    s += __shfl_xor_sync(0xffffffffu, s, 4);
    s += __shfl_xor_sync(0xffffffffu, s, 2);
    s += __shfl_xor_sync(0xffffffffu, s, 1);
    return s;
}
// packed fp32x2 ops (sm_103a; ptxas never auto-fuses these)
__device__ __forceinline__ unsigned long long pack2(float x, float y) {
    unsigned long long r;
    asm("mov.b64 %0, {%1, %2};" : "=l"(r) : "f"(x), "f"(y));
    return r;
}
__device__ __forceinline__ float2 unpack2f(unsigned long long v) {
    float2 r;
    asm("mov.b64 {%0, %1}, %2;" : "=f"(r.x), "=f"(r.y) : "l"(v));
    return r;
}
__device__ __forceinline__ unsigned long long ffma2(unsigned long long a, unsigned long long b,
                                                    unsigned long long c) {
    unsigned long long d;
    asm("fma.rn.f32x2 %0, %1, %2, %3;" : "=l"(d) : "l"(a), "l"(b), "l"(c));
    return d;
}

// L2-normalize one node per warp + zero degw (layer 0 prep)
__device__ __forceinline__ void normalize_body(const float* __restrict__ X, int N, int vid) {
    int node = vid >> 5;
    if (node >= N) return;
    int lane = vid & 31;
    float4 v = ((const float4*)(X + (size_t)node * F))[lane];
    float ss = v.x * v.x + v.y * v.y + v.z * v.z + v.w * v.w;
    ss = warpSum(ss);
    float inv = 1.f / fmaxf(sqrtf(ss), 1e-12f);
    v.x *= inv; v.y *= inv; v.z *= inv; v.w *= inv;
    ((float4*)(d_xn + (size_t)node * F))[lane] = v;
    if (lane == 0) d_degw[node] = 0.f;
}

// ---------------- CSR build ----------------
__global__ void combo_hist_norm_kernel(const int* __restrict__ erow, const int* __restrict__ ecol,
                                       int E, const float* __restrict__ X, int N,
                                       int histBlocks, int Ehalf) {
    if ((int)blockIdx.x < histBlocks) {
        int e = blockIdx.x * blockDim.x + threadIdx.x;
        if (e < Ehalf) {
            atomicAdd(&d_hist2[erow[e]], 1);
            atomicAdd(&d_hist2[(NMAX + 1) + ecol[e]], 1);
        }
        int e2 = e + Ehalf;
        if (e2 < E) {
            atomicAdd(&d_hist2[erow[e2]], 1);
            atomicAdd(&d_hist2[(NMAX + 1) + ecol[e2]], 1);
        }
    } else {
        int vid = (blockIdx.x - histBlocks) * blockDim.x + threadIdx.x;
        normalize_body(X, N, vid);
    }
}
// per-1024 chunk inclusive scan; also RE-ZEROS hist after reading (invariant for next call)
__global__ void scan1_kernel(int n) {
    __shared__ int tsum[256];
    int y = blockIdx.y;
    int* hist = d_hist2 + y * (NMAX + 1);
    int* start = d_start2 + y * (NMAX + 1);
    int* bsum  = d_bsum2 + y * 64;
    int b = blockIdx.x, t = threadIdx.x;
    int base = b * 1024 + t * 4;
    int v0 = (base + 0 < n) ? hist[base + 0] : 0;
    int v1 = (base + 1 < n) ? hist[base + 1] : 0;
    int v2 = (base + 2 < n) ? hist[base + 2] : 0;
    int v3 = (base + 3 < n) ? hist[base + 3] : 0;
    if (base + 0 < n) hist[base + 0] = 0;
    if (base + 1 < n) hist[base + 1] = 0;
    if (base + 2 < n) hist[base + 2] = 0;
    if (base + 3 < n) hist[base + 3] = 0;
    int s0 = v0, s1 = s0 + v1, s2 = s1 + v2, s3 = s2 + v3;
    tsum[t] = s3;
    __syncthreads();
    for (int off = 1; off < 256; off <<= 1) {
        int x = (t >= off) ? tsum[t - off] : 0;
        __syncthreads();
        tsum[t] += x;
        __syncthreads();
    }
    int add = (t > 0) ? tsum[t - 1] : 0;
    if (base + 0 < n) start[base + 1] = s0 + add;
    if (base + 1 < n) start[base + 2] = s1 + add;
    if (base + 2 < n) start[base + 3] = s2 + add;
    if (base + 3 < n) start[base + 4] = s3 + add;
    if (t == 255) bsum[b] = tsum[255];
}
// adds cross-chunk bases; block-sums staged in smem + warp-scanned
__global__ void scan3_kernel(int n, int nblocks) {
    __shared__ int sb[64];
    int y = blockIdx.y;
    int* start = d_start2 + y * (NMAX + 1);
    int* coff  = d_coff2 + y * NMAX;
    const int* bsum = d_bsum2 + y * 64;
    int t = threadIdx.x;
    if (t < 64) sb[t] = (t < nblocks) ? bsum[t] : 0;
    __syncthreads();
    if (t < 32) {
        int a = sb[t], b = sb[t + 32];
#pragma unroll
        for (int off = 1; off < 32; off <<= 1) {
            int v = __shfl_up_sync(0xffffffffu, a, off);
            if (t >= off) a += v;
        }
        int totalA = __shfl_sync(0xffffffffu, a, 31);
#pragma unroll
        for (int off = 1; off < 32; off <<= 1) {
            int v = __shfl_up_sync(0xffffffffu, b, off);
            if (t >= off) b += v;
        }
        int exA = __shfl_up_sync(0xffffffffu, a, 1);
        int exB = __shfl_up_sync(0xffffffffu, b, 1);
        if (t == 0) { exA = 0; exB = 0; }
        sb[t] = exA;
        sb[t + 32] = exB + totalA;
    }
    __syncthreads();
    int i = blockIdx.x * blockDim.x + t;
    if (i < n) {
        int v = start[i + 1] + sb[i >> 10];
        start[i + 1] = v;
        if (i + 1 < n) coff[i + 1] = v;
        if (i == 0) { coff[0] = 0; start[0] = 0; }
    }
}
__global__ void scatter2_kernel(const int* __restrict__ erow, const int* __restrict__ ecol,
                                int E, int Ehalf) {
    int e = blockIdx.x * blockDim.x + threadIdx.x;
    if (e < Ehalf) {
        int r = erow[e], c = ecol[e];
        int pr = atomicAdd(&d_coff2[r], 1);
        int pc = atomicAdd(&d_coff2[NMAX + c], 1);
        d_rcsr[pr] = make_int2(c, pc);
        d_ccsr_src[pc] = r;
    }
    int e2 = e + Ehalf;
    if (e2 < E) {
        int r = erow[e2], c = ecol[e2];
        int pr = atomicAdd(&d_coff2[r], 1);
        int pc = atomicAdd(&d_coff2[NMAX + c], 1);
        d_rcsr[pr] = make_int2(c, pc);
        d_ccsr_src[pc] = r;
    }
}

// ---------------- per-layer kernels ----------------
// Fused sim + weight: warp per source row, half-warp per edge, 4 edges in flight (R12 best).
__global__ void simweight_kernel(const float* __restrict__ gate, int layer, int N) {
    int gid = blockIdx.x * blockDim.x + threadIdx.x;
    int r = gid >> 5;
    if (r >= N) return;
    int lane = gid & 31;
    int half = lane >> 4;
    int hl = lane & 15;
    int p0 = d_start2[r], p1 = d_start2[r + 1];
    const float4* xrp = (const float4*)(d_xn + (size_t)r * F);
    float4 xa = xrp[hl * 2];
    float4 xb = xrp[hl * 2 + 1];
    float rs = 0.f;
    int cnt = 0;
    int p = p0;
    for (; p + 3 < p1; p += 4) {
        int cA = d_rcsr[p + half].x;
        int cB = d_rcsr[p + 2 + half].x;
        const float4* cpA = (const float4*)(d_xn + (size_t)cA * F);
        const float4* cpB = (const float4*)(d_xn + (size_t)cB * F);
        float4 a0 = cpA[hl * 2], a1 = cpA[hl * 2 + 1];
        float4 b0 = cpB[hl * 2], b1 = cpB[hl * 2 + 1];
        float sA = a0.x * xa.x + a0.y * xa.y + a0.z * xa.z + a0.w * xa.w
                 + a1.x * xb.x + a1.y * xb.y + a1.z * xb.z + a1.w * xb.w;
        float sB = b0.x * xa.x + b0.y * xa.y + b0.z * xa.z + b0.w * xa.w
                 + b1.x * xb.x + b1.y * xb.y + b1.z * xb.z + b1.w * xb.w;
        sA = halfSum(sA);
        sB = halfSum(sB);
        if (cA == r || sA < 0.1f) sA = 0.f;
        if (cB == r || sB < 0.1f) sB = 0.f;
        if (hl == 0) {
            d_simr[p + half] = sA;
            d_simr[p + 2 + half] = sB;
        }
        rs += sA + sB;
        cnt += (sA > 0.f) + (sB > 0.f);
    }
    for (; p + 1 < p1; p += 2) {
        int c = d_rcsr[p + half].x;
        const float4* cp = (const float4*)(d_xn + (size_t)c * F);
        float4 a = cp[hl * 2];
        float4 b = cp[hl * 2 + 1];
        float s = a.x * xa.x + a.y * xa.y + a.z * xa.z + a.w * xa.w
                + b.x * xb.x + b.y * xb.y + b.z * xb.z + b.w * xb.w;
        s = halfSum(s);
        if (c == r || s < 0.1f) s = 0.f;
        if (hl == 0) d_simr[p + half] = s;
        rs += s;
        cnt += (s > 0.f);
    }
    if (p < p1) {
        int c = d_rcsr[p].x;
        const float4* cp = (const float4*)(d_xn + (size_t)c * F);
        float4 a = cp[hl * 2];
        float4 b = cp[hl * 2 + 1];
        float s = a.x * xa.x + a.y * xa.y + a.z * xa.z + a.w * xa.w
                + b.x * xb.x + b.y * xb.y + b.z * xb.z + b.w * xb.w;
        s = halfSum(s);
        if (c == r || s < 0.1f) s = 0.f;
        if (lane == 0) d_simr[p] = s;
        if (half == 0) { rs += s; cnt += (s > 0.f); }
    }
    rs += __shfl_xor_sync(0xffffffffu, rs, 16);
    cnt += __shfl_xor_sync(0xffffffffu, cnt, 16);
    float lamw = 1.f / ((float)cnt + 1.f);
    float g = (layer > 0) ? gate[layer - 1] : 0.f;
    for (int q = p0 + lane; q < p1; q += 32) {
        int2 dc = d_rcsr[q];
        float wraw;
        if (dc.x == r) {
            wraw = lamw;
        } else {
            float s = d_simr[q];
            wraw = (s > 0.f) ? s / rs : 0.f;
        }
        float en = __expf(wraw);   // exp applied to ALL edges (exp(0)=1 for pruned)
        float w;
        if (layer == 0) {
            d_adjr[q] = en;
            w = en;
        } else {
            w = g * d_adjr[q] + (1.f - g) * en;
        }
        d_wcsr[dc.y] = w;
        atomicAdd(&d_degw[dc.x], w);
    }
}

// f32x2 row-pair GEMM v3: 128 rows x 64 cols per block, 256 threads (8 warps x 8 row-pairs).
// X staged as row-pair u64 (broadcast LDS.128 reads); W staged SCALAR (lane-consecutive,
// 1 crossbar phase), duplicated at use via pack2 on the idle ALU pipe. acc = 16 u64 = 32 regs.
// 96KB smem -> 2 blocks/SM. FMA-pipe-bound at 128 MACs/cyc/SM (2x scalar FFMA).
#define GX_SMEM (64 * 128 * 8 + 128 * 64 * 4)   // Xp 64KB + Ws 32KB = 96KB
__global__ void __launch_bounds__(256) gemm128x2_kernel(const float* __restrict__ X,
                                                        const float* __restrict__ Wg, int N) {
    extern __shared__ char smc[];
    unsigned long long* Xp = (unsigned long long*)smc;        // [64 rp][128 k] (rowA_k, rowB_k)
    float* Ws = (float*)(smc + 64 * 128 * 8);                 // [128 k][64 c]
    int t = threadIdx.x, w = t >> 5, lane = t & 31;
    int ct0 = blockIdx.y * 64;
    int rowBase = blockIdx.x * 128;
    // stage W scalar: i = k*64 + c
    for (int i = t; i < 128 * 64; i += 256) {
        int k = i >> 6, c = i & 63;
        Ws[i] = Wg[k * 128 + ct0 + c];
    }
    // stage X row pairs: i = rp*128 + k (k fastest -> coalesced row reads)
    for (int i = t; i < 64 * 128; i += 256) {
        int rp = i >> 7, k = i & 127;
        int rA = rowBase + 2 * rp, rB = rA + 1;
        float a = (rA < N) ? X[(size_t)rA * 128 + k] : 0.f;
        float b = (rB < N) ? X[(size_t)rB * 128 + k] : 0.f;
        Xp[i] = pack2(a, b);
    }
    __syncthreads();
    // warp w handles row-pairs [w*8, w*8+8), cols ct0+lane and ct0+lane+32
    unsigned long long acc0[8], acc1[8];
#pragma unroll
    for (int i = 0; i < 8; i++) { acc0[i] = 0ull; acc1[i] = 0ull; }
    const unsigned long long* xb = Xp + (w * 8) * 128;
#pragma unroll 2
    for (int k = 0; k < 128; k += 2) {
        float w0a = Ws[k * 64 + lane];
        float w1a = Ws[k * 64 + lane + 32];
        float w0b = Ws[(k + 1) * 64 + lane];
        float w1b = Ws[(k + 1) * 64 + lane + 32];
        unsigned long long W0a = pack2(w0a, w0a);
        unsigned long long W1a = pack2(w1a, w1a);
        unsigned long long W0b = pack2(w0b, w0b);
        unsigned long long W1b = pack2(w1b, w1b);
#pragma unroll
        for (int rp = 0; rp < 8; rp++) {
            ulonglong2 xp = *(const ulonglong2*)(xb + rp * 128 + k);   // broadcast 16B
            acc0[rp] = ffma2(xp.x, W0a, acc0[rp]);
            acc1[rp] = ffma2(xp.x, W1a, acc1[rp]);
            acc0[rp] = ffma2(xp.y, W0b, acc0[rp]);
            acc1[rp] = ffma2(xp.y, W1b, acc1[rp]);
        }
    }
#pragma unroll
    for (int rp = 0; rp < 8; rp++) {
        int rA = rowBase + 2 * (w * 8 + rp), rB = rA + 1;
        float2 c0 = unpack2f(acc0[rp]);   // (.x rowA, .y rowB) at col ct0+lane
        float2 c1 = unpack2f(acc1[rp]);   // at col ct0+lane+32
        if (rA < N) {
            float dw = d_degw[rA];
            float sc = (dw > 0.f) ? rsqrtf(dw) : 0.f;
            d_hw[(size_t)rA * 128 + ct0 + lane]      = c0.x * sc;
            d_hw[(size_t)rA * 128 + ct0 + lane + 32] = c1.x * sc;
        }
        if (rB < N) {
            float dw = d_degw[rB];
            float sc = (dw > 0.f) ? rsqrtf(dw) : 0.f;
            d_hw[(size_t)rB * 128 + ct0 + lane]      = c0.y * sc;
            d_hw[(size_t)rB * 128 + ct0 + lane + 32] = c1.y * sc;
        }
    }
}

// layer-2 GEMM (FOUT=40), scalar (small)
template <int FOUT, int CT>
__global__ void __launch_bounds__(256) gemm_kernel(const float* __restrict__ X,
                                                   const float* __restrict__ Wg, int N) {
    __shared__ float Ws[128 * CT];
    __shared__ float Xs[8][4][128];
    int t = threadIdx.x, w = t >> 5, lane = t & 31;
    int ct0 = blockIdx.y * CT;
    for (int i = t; i < 128 * CT; i += 256) {
        int k = i / CT, c = i - k * CT;
        Ws[i] = Wg[k * FOUT + ct0 + c];
    }
    int rowBase = blockIdx.x * 32 + w * 4;
#pragma unroll
    for (int r = 0; r < 4; r++) {
        int row = rowBase + r;
        float4 v = make_float4(0.f, 0.f, 0.f, 0.f);
        if (row < N) v = ((const float4*)(X + (size_t)row * 128))[lane];
        *(float4*)&Xs[w][r][lane * 4] = v;
    }
    __syncthreads();
    const bool has1 = (lane + 32) < CT;
    float a0[4] = {0.f, 0.f, 0.f, 0.f};
    float a1[4] = {0.f, 0.f, 0.f, 0.f};
#pragma unroll 4
    for (int k0 = 0; k0 < 128; k0 += 4) {
        float4 xv[4];
#pragma unroll
        for (int r = 0; r < 4; r++) xv[r] = *(const float4*)&Xs[w][r][k0];
#pragma unroll
        for (int kk = 0; kk < 4; kk++) {
            float w0 = Ws[(k0 + kk) * CT + lane];
            float w1 = has1 ? Ws[(k0 + kk) * CT + lane + 32] : 0.f;
#pragma unroll
            for (int r = 0; r < 4; r++) {
                float xs = (kk == 0) ? xv[r].x : (kk == 1) ? xv[r].y : (kk == 2) ? xv[r].z : xv[r].w;
                a0[r] = fmaf(xs, w0, a0[r]);
                a1[r] = fmaf(xs, w1, a1[r]);
            }
        }
    }
#pragma unroll
    for (int r = 0; r < 4; r++) {
        int row = rowBase + r;
        if (row < N) {
            float dw = d_degw[row];
            float sc = (dw > 0.f) ? rsqrtf(dw) : 0.f;
            d_hw[(size_t)row * FOUT + ct0 + lane] = a0[r] * sc;
            if (has1) d_hw[(size_t)row * FOUT + ct0 + lane + 32] = a1[r] * sc;
        }
    }
}

// Fused aggregation + relu + L2-normalize + degw re-zero; 4 edges in flight (R12 best).
__global__ void gather128_norm_kernel(const float* __restrict__ bias, float* __restrict__ out, int N) {
    int gid = blockIdx.x * blockDim.x + threadIdx.x;
    int node = gid >> 5;
    if (node >= N) return;
    int lane = gid & 31;
    int p0 = d_start2[(NMAX + 1) + node], p1 = d_start2[(NMAX + 1) + node + 1];
    float dw = d_degw[node];
    float dc = (dw > 0.f) ? rsqrtf(dw) : 0.f;
    float4 acc = make_float4(0.f, 0.f, 0.f, 0.f);
    int p = p0;
    for (; p + 3 < p1; p += 4) {
        int r0 = d_ccsr_src[p],     r1 = d_ccsr_src[p + 1];
        int r2 = d_ccsr_src[p + 2], r3 = d_ccsr_src[p + 3];
        float w0 = d_wcsr[p],     w1 = d_wcsr[p + 1];
        float w2 = d_wcsr[p + 2], w3 = d_wcsr[p + 3];
        float4 h0 = ((const float4*)(d_hw + (size_t)r0 * 128))[lane];
        float4 h1 = ((const float4*)(d_hw + (size_t)r1 * 128))[lane];
        float4 h2 = ((const float4*)(d_hw + (size_t)r2 * 128))[lane];
        float4 h3 = ((const float4*)(d_hw + (size_t)r3 * 128))[lane];
        acc.x = fmaf(w0, h0.x, fmaf(w1, h1.x, fmaf(w2, h2.x, fmaf(w3, h3.x, acc.x))));
        acc.y = fmaf(w0, h0.y, fmaf(w1, h1.y, fmaf(w2, h2.y, fmaf(w3, h3.y, acc.y))));
        acc.z = fmaf(w0, h0.z, fmaf(w1, h1.z, fmaf(w2, h2.z, fmaf(w3, h3.z, acc.z))));
        acc.w = fmaf(w0, h0.w, fmaf(w1, h1.w, fmaf(w2, h2.w, fmaf(w3, h3.w, acc.w))));
    }
    for (; p < p1; p++) {
        int r0 = d_ccsr_src[p];
        float w0 = d_wcsr[p];
        float4 h0 = ((const float4*)(d_hw + (size_t)r0 * 128))[lane];
        acc.x = fmaf(w0, h0.x, acc.x);
        acc.y = fmaf(w0, h0.y, acc.y);
        acc.z = fmaf(w0, h0.z, acc.z);
        acc.w = fmaf(w0, h0.w, acc.w);
    }
    float4 bv = ((const float4*)bias)[lane];
    acc.x = fmaxf(fmaf(acc.x, dc, bv.x), 0.f);
    acc.y = fmaxf(fmaf(acc.y, dc, bv.y), 0.f);
    acc.z = fmaxf(fmaf(acc.z, dc, bv.z), 0.f);
    acc.w = fmaxf(fmaf(acc.w, dc, bv.w), 0.f);
    ((float4*)(out + (size_t)node * 128))[lane] = acc;
    float ss = acc.x * acc.x + acc.y * acc.y + acc.z * acc.z + acc.w * acc.w;
    ss = warpSum(ss);
    float inv = 1.f / fmaxf(sqrtf(ss), 1e-12f);
    float4 xv = make_float4(acc.x * inv, acc.y * inv, acc.z * inv, acc.w * inv);
    ((float4*)(d_xn + (size_t)node * F))[lane] = xv;
    if (lane == 0) d_degw[node] = 0.f;
}

// Final layer: 40-class gather + fused log_softmax (warp/node), 2 edges in flight
__global__ void gather40_lsm_kernel(const float* __restrict__ bias, float* __restrict__ out, int N) {
    int gid = blockIdx.x * blockDim.x + threadIdx.x;
    int node = gid >> 5;
    if (node >= N) return;
    int lane = gid & 31;
    int p0 = d_start2[(NMAX + 1) + node], p1 = d_start2[(NMAX + 1) + node + 1];
    float dw = d_degw[node];
    float dc = (dw > 0.f) ? rsqrtf(dw) : 0.f;
    bool has1 = lane < 8;
    float a0 = 0.f, a1 = 0.f;
    int p = p0;
    for (; p + 1 < p1; p += 2) {
        int rA = d_ccsr_src[p], rB = d_ccsr_src[p + 1];
        float wA = d_wcsr[p], wB = d_wcsr[p + 1];
        const float* hA = d_hw + (size_t)rA * 40;
        const float* hB = d_hw + (size_t)rB * 40;
        float vA0 = hA[lane], vB0 = hB[lane];
        float vA1 = has1 ? hA[lane + 32] : 0.f;
        float vB1 = has1 ? hB[lane + 32] : 0.f;
        a0 = fmaf(wA, vA0, fmaf(wB, vB0, a0));
        a1 = fmaf(wA, vA1, fmaf(wB, vB1, a1));
    }
    if (p < p1) {
        int rA = d_ccsr_src[p];
        float wA = d_wcsr[p];
        const float* hA = d_hw + (size_t)rA * 40;
        a0 = fmaf(wA, hA[lane], a0);
        if (has1) a1 = fmaf(wA, hA[lane + 32], a1);
    }
    a0 = fmaf(a0, dc, bias[lane]);
    float v1 = -INFINITY;
    if (has1) { a1 = fmaf(a1, dc, bias[lane + 32]); v1 = a1; }
    float m = warpMax(fmaxf(a0, v1));
    float s = expf(a0 - m) + (has1 ? expf(a1 - m) : 0.f);
    s = warpSum(s);
    float lse = m + logf(s);
    out[(size_t)node * 40 + lane] = a0 - lse;
    if (has1) out[(size_t)node * 40 + lane + 32] = a1 - lse;
}

// ---------------- driver ----------------
extern "C" void kernel_launch(void* const* d_in, const int* in_sizes, int n_in,
                              void* d_out, int out_size) {
    const float* x    = (const float*)d_in[0];
    const float* gate = (const float*)d_in[1];
    const float* W0   = (const float*)d_in[2];
    const float* b0   = (const float*)d_in[3];
    const float* W1   = (const float*)d_in[4];
    const float* b1   = (const float*)d_in[5];
    const float* W2   = (const float*)d_in[6];
    const float* b2   = (const float*)d_in[7];
    const int*   ei   = (const int*)d_in[8];

    int N = in_sizes[0] / F;
    int E = in_sizes[8] / 2;
    const int* erow = ei;
    const int* ecol = ei + E;
    float* out = (float*)d_out;

    void* hp_v = nullptr;
    cudaGetSymbolAddress(&hp_v, d_h);
    float* hp = (float*)hp_v;

    cudaFuncSetAttribute(gemm128x2_kernel, cudaFuncAttributeMaxDynamicSharedMemorySize, GX_SMEM);

    const int TB = 256;
    int blkN  = (N + TB - 1) / TB;
    int blkWN = ((N * 32) + TB - 1) / TB;
    int nchunks = (N + 1023) / 1024;
    int Ehalf = (E + 1) / 2;
    int blkEh = (Ehalf + TB - 1) / TB;

    // ---- build both CSRs; normalize overlapped with hist ----
    combo_hist_norm_kernel<<<blkEh + blkWN, TB>>>(erow, ecol, E, x, N, blkEh, Ehalf);
    scan1_kernel<<<dim3(nchunks, 2), 256>>>(N);
    scan3_kernel<<<dim3(blkN, 2), TB>>>(N, nchunks);
    scatter2_kernel<<<blkEh, TB>>>(erow, ecol, E, Ehalf);

    dim3 ggrid2((N + 127) / 128, 2);   // f32x2 gemm: 128 rows x 64 cols per block
    dim3 ggrid40((N + 31) / 32, 1);

    // ---- layer 0 ----
    simweight_kernel<<<blkWN, TB>>>(gate, 0, N);
    gemm128x2_kernel<<<ggrid2, 256, GX_SMEM>>>(x, W0, N);
    gather128_norm_kernel<<<blkWN, TB>>>(b0, hp, N);

    // ---- layer 1 ----
    simweight_kernel<<<blkWN, TB>>>(gate, 1, N);
    gemm128x2_kernel<<<ggrid2, 256, GX_SMEM>>>(hp, W1, N);
    gather128_norm_kernel<<<blkWN, TB>>>(b1, hp, N);

    // ---- layer 2 ----
    simweight_kernel<<<blkWN, TB>>>(gate, 2, N);
    gemm_kernel<40, 40><<<ggrid40, 256>>>(hp, W2, N);
    gather40_lsm_kernel<<<blkWN, TB>>>(b2, out, N);
}

// round 16
// speedup vs baseline: 1.3455x; 1.0388x over previous
#include <cuda_runtime.h>
#include <math.h>
#include <stdint.h>

#define NMAX 50000
#define EMAX 850000
#define F 128

// ---------------- scratch ----------------
__device__ float d_xn[NMAX * F];       // L2-normalized activations (the ONLY feature stream)
__device__ float d_hw[NMAX * F];
__device__ float d_hnorm[NMAX];        // ||h|| per row (h = xn * hnorm)
__device__ float d_simr[EMAX];         // sims, row-CSR ordered
__device__ float d_adjr[EMAX];         // base attention (exp), row-CSR ordered
__device__ float d_wcsr[EMAX];         // current edge weight, col-CSR ordered
__device__ float d_degw[NMAX];
// two CSRs: [0]=by row, [1]=by col
__device__ int   d_hist2 [2 * (NMAX + 1)];   // zero-init at load; re-zeroed by scan1 each call
__device__ int   d_start2[2 * (NMAX + 1)];
__device__ int   d_coff2 [2 * NMAX];
__device__ int   d_bsum2 [2 * 64];
__device__ int2  d_rcsr[EMAX];         // row-CSR: {col endpoint, col-CSR pos}
__device__ int   d_ccsr_src[EMAX];     // col-CSR: row endpoint

// ---------------- helpers ----------------
__device__ __forceinline__ float warpSum(float v) {
    v += __shfl_xor_sync(0xffffffffu, v, 16);
    v += __shfl_xor_sync(0xffffffffu, v, 8);
    v += __shfl_xor_sync(0xffffffffu, v, 4);
    v += __shfl_xor_sync(0xffffffffu, v, 2);
    v += __shfl_xor_sync(0xffffffffu, v, 1);
    return v;
}
__device__ __forceinline__ float warpMax(float v) {
    v = fmaxf(v, __shfl_xor_sync(0xffffffffu, v, 16));
    v = fmaxf(v, __shfl_xor_sync(0xffffffffu, v, 8));
    v = fmaxf(v, __shfl_xor_sync(0xffffffffu, v, 4));
    v = fmaxf(v, __shfl_xor_sync(0xffffffffu, v, 2));
    v = fmaxf(v, __shfl_xor_sync(0xffffffffu, v, 1));
    return v;
}
__device__ __forceinline__ float halfSum(float s) {
    s += __shfl_xor_sync(0xffffffffu, s, 8);
    s += __shfl_xor_sync(0xffffffffu, s, 4);
    s += __shfl_xor_sync(0xffffffffu, s, 2);
    s += __shfl_xor_sync(0xffffffffu, s, 1);
    return s;
}
// packed fp32x2 ops (sm_103a; ptxas never auto-fuses these)
__device__ __forceinline__ unsigned long long pack2(float x, float y) {
    unsigned long long r;
    asm("mov.b64 %0, {%1, %2};" : "=l"(r) : "f"(x), "f"(y));
    return r;
}
__device__ __forceinline__ float2 unpack2f(unsigned long long v) {
    float2 r;
    asm("mov.b64 {%0, %1}, %2;" : "=f"(r.x), "=f"(r.y) : "l"(v));
    return r;
}
__device__ __forceinline__ unsigned long long ffma2(unsigned long long a, unsigned long long b,
                                                    unsigned long long c) {
    unsigned long long d;
    asm("fma.rn.f32x2 %0, %1, %2, %3;" : "=l"(d) : "l"(a), "l"(b), "l"(c));
    return d;
}

// L2-normalize one node per warp + zero degw (layer 0 prep)
__device__ __forceinline__ void normalize_body(const float* __restrict__ X, int N, int vid) {
    int node = vid >> 5;
    if (node >= N) return;
    int lane = vid & 31;
    float4 v = ((const float4*)(X + (size_t)node * F))[lane];
    float ss = v.x * v.x + v.y * v.y + v.z * v.z + v.w * v.w;
    ss = warpSum(ss);
    float inv = 1.f / fmaxf(sqrtf(ss), 1e-12f);
    v.x *= inv; v.y *= inv; v.z *= inv; v.w *= inv;
    ((float4*)(d_xn + (size_t)node * F))[lane] = v;
    if (lane == 0) d_degw[node] = 0.f;
}

// ---------------- CSR build ----------------
__global__ void combo_hist_norm_kernel(const int* __restrict__ erow, const int* __restrict__ ecol,
                                       int E, const float* __restrict__ X, int N,
                                       int histBlocks, int Ehalf) {
    if ((int)blockIdx.x < histBlocks) {
        int e = blockIdx.x * blockDim.x + threadIdx.x;
        if (e < Ehalf) {
            atomicAdd(&d_hist2[erow[e]], 1);
            atomicAdd(&d_hist2[(NMAX + 1) + ecol[e]], 1);
        }
        int e2 = e + Ehalf;
        if (e2 < E) {
            atomicAdd(&d_hist2[erow[e2]], 1);
            atomicAdd(&d_hist2[(NMAX + 1) + ecol[e2]], 1);
        }
    } else {
        int vid = (blockIdx.x - histBlocks) * blockDim.x + threadIdx.x;
        normalize_body(X, N, vid);
    }
}
// per-1024 chunk inclusive scan; also RE-ZEROS hist after reading (invariant for next call)
__global__ void scan1_kernel(int n) {
    __shared__ int tsum[256];
    int y = blockIdx.y;
    int* hist = d_hist2 + y * (NMAX + 1);
    int* start = d_start2 + y * (NMAX + 1);
    int* bsum  = d_bsum2 + y * 64;
    int b = blockIdx.x, t = threadIdx.x;
    int base = b * 1024 + t * 4;
    int v0 = (base + 0 < n) ? hist[base + 0] : 0;
    int v1 = (base + 1 < n) ? hist[base + 1] : 0;
    int v2 = (base + 2 < n) ? hist[base + 2] : 0;
    int v3 = (base + 3 < n) ? hist[base + 3] : 0;
    if (base + 0 < n) hist[base + 0] = 0;
    if (base + 1 < n) hist[base + 1] = 0;
    if (base + 2 < n) hist[base + 2] = 0;
    if (base + 3 < n) hist[base + 3] = 0;
    int s0 = v0, s1 = s0 + v1, s2 = s1 + v2, s3 = s2 + v3;
    tsum[t] = s3;
    __syncthreads();
    for (int off = 1; off < 256; off <<= 1) {
        int x = (t >= off) ? tsum[t - off] : 0;
        __syncthreads();
        tsum[t] += x;
        __syncthreads();
    }
    int add = (t > 0) ? tsum[t - 1] : 0;
    if (base + 0 < n) start[base + 1] = s0 + add;
    if (base + 1 < n) start[base + 2] = s1 + add;
    if (base + 2 < n) start[base + 3] = s2 + add;
    if (base + 3 < n) start[base + 4] = s3 + add;
    if (t == 255) bsum[b] = tsum[255];
}
// adds cross-chunk bases; block-sums staged in smem + warp-scanned
__global__ void scan3_kernel(int n, int nblocks) {
    __shared__ int sb[64];
    int y = blockIdx.y;
    int* start = d_start2 + y * (NMAX + 1);
    int* coff  = d_coff2 + y * NMAX;
    const int* bsum = d_bsum2 + y * 64;
    int t = threadIdx.x;
    if (t < 64) sb[t] = (t < nblocks) ? bsum[t] : 0;
    __syncthreads();
    if (t < 32) {
        int a = sb[t], b = sb[t + 32];
#pragma unroll
        for (int off = 1; off < 32; off <<= 1) {
            int v = __shfl_up_sync(0xffffffffu, a, off);
            if (t >= off) a += v;
        }
        int totalA = __shfl_sync(0xffffffffu, a, 31);
#pragma unroll
        for (int off = 1; off < 32; off <<= 1) {
            int v = __shfl_up_sync(0xffffffffu, b, off);
            if (t >= off) b += v;
        }
        int exA = __shfl_up_sync(0xffffffffu, a, 1);
        int exB = __shfl_up_sync(0xffffffffu, b, 1);
        if (t == 0) { exA = 0; exB = 0; }
        sb[t] = exA;
        sb[t + 32] = exB + totalA;
    }
    __syncthreads();
    int i = blockIdx.x * blockDim.x + t;
    if (i < n) {
        int v = start[i + 1] + sb[i >> 10];
        start[i + 1] = v;
        if (i + 1 < n) coff[i + 1] = v;
        if (i == 0) { coff[0] = 0; start[0] = 0; }
    }
}
__global__ void scatter2_kernel(const int* __restrict__ erow, const int* __restrict__ ecol,
                                int E, int Ehalf) {
    int e = blockIdx.x * blockDim.x + threadIdx.x;
    if (e < Ehalf) {
        int r = erow[e], c = ecol[e];
        int pr = atomicAdd(&d_coff2[r], 1);
        int pc = atomicAdd(&d_coff2[NMAX + c], 1);
        d_rcsr[pr] = make_int2(c, pc);
        d_ccsr_src[pc] = r;
    }
    int e2 = e + Ehalf;
    if (e2 < E) {
        int r = erow[e2], c = ecol[e2];
        int pr = atomicAdd(&d_coff2[r], 1);
        int pc = atomicAdd(&d_coff2[NMAX + c], 1);
        d_rcsr[pr] = make_int2(c, pc);
        d_ccsr_src[pc] = r;
    }
}

// ---------------- per-layer kernels ----------------
// Fused sim + weight: warp per source row, half-warp per edge, 4 edges in flight (R12 best).
__global__ void simweight_kernel(const float* __restrict__ gate, int layer, int N) {
    int gid = blockIdx.x * blockDim.x + threadIdx.x;
    int r = gid >> 5;
    if (r >= N) return;
    int lane = gid & 31;
    int half = lane >> 4;
    int hl = lane & 15;
    int p0 = d_start2[r], p1 = d_start2[r + 1];
    const float4* xrp = (const float4*)(d_xn + (size_t)r * F);
    float4 xa = xrp[hl * 2];
    float4 xb = xrp[hl * 2 + 1];
    float rs = 0.f;
    int cnt = 0;
    int p = p0;
    for (; p + 3 < p1; p += 4) {
        int cA = d_rcsr[p + half].x;
        int cB = d_rcsr[p + 2 + half].x;
        const float4* cpA = (const float4*)(d_xn + (size_t)cA * F);
        const float4* cpB = (const float4*)(d_xn + (size_t)cB * F);
        float4 a0 = cpA[hl * 2], a1 = cpA[hl * 2 + 1];
        float4 b0 = cpB[hl * 2], b1 = cpB[hl * 2 + 1];
        float sA = a0.x * xa.x + a0.y * xa.y + a0.z * xa.z + a0.w * xa.w
                 + a1.x * xb.x + a1.y * xb.y + a1.z * xb.z + a1.w * xb.w;
        float sB = b0.x * xa.x + b0.y * xa.y + b0.z * xa.z + b0.w * xa.w
                 + b1.x * xb.x + b1.y * xb.y + b1.z * xb.z + b1.w * xb.w;
        sA = halfSum(sA);
        sB = halfSum(sB);
        if (cA == r || sA < 0.1f) sA = 0.f;
        if (cB == r || sB < 0.1f) sB = 0.f;
        if (hl == 0) {
            d_simr[p + half] = sA;
            d_simr[p + 2 + half] = sB;
        }
        rs += sA + sB;
        cnt += (sA > 0.f) + (sB > 0.f);
    }
    for (; p + 1 < p1; p += 2) {
        int c = d_rcsr[p + half].x;
        const float4* cp = (const float4*)(d_xn + (size_t)c * F);
        float4 a = cp[hl * 2];
        float4 b = cp[hl * 2 + 1];
        float s = a.x * xa.x + a.y * xa.y + a.z * xa.z + a.w * xa.w
                + b.x * xb.x + b.y * xb.y + b.z * xb.z + b.w * xb.w;
        s = halfSum(s);
        if (c == r || s < 0.1f) s = 0.f;
        if (hl == 0) d_simr[p + half] = s;
        rs += s;
        cnt += (s > 0.f);
    }
    if (p < p1) {
        int c = d_rcsr[p].x;
        const float4* cp = (const float4*)(d_xn + (size_t)c * F);
        float4 a = cp[hl * 2];
        float4 b = cp[hl * 2 + 1];
        float s = a.x * xa.x + a.y * xa.y + a.z * xa.z + a.w * xa.w
                + b.x * xb.x + b.y * xb.y + b.z * xb.z + b.w * xb.w;
        s = halfSum(s);
        if (c == r || s < 0.1f) s = 0.f;
        if (lane == 0) d_simr[p] = s;
        if (half == 0) { rs += s; cnt += (s > 0.f); }
    }
    rs += __shfl_xor_sync(0xffffffffu, rs, 16);
    cnt += __shfl_xor_sync(0xffffffffu, cnt, 16);
    float lamw = 1.f / ((float)cnt + 1.f);
    float g = (layer > 0) ? gate[layer - 1] : 0.f;
    for (int q = p0 + lane; q < p1; q += 32) {
        int2 dc = d_rcsr[q];
        float wraw;
        if (dc.x == r) {
            wraw = lamw;
        } else {
            float s = d_simr[q];
            wraw = (s > 0.f) ? s / rs : 0.f;
        }
        float en = __expf(wraw);   // exp applied to ALL edges (exp(0)=1 for pruned)
        float w;
        if (layer == 0) {
            d_adjr[q] = en;
            w = en;
        } else {
            w = g * d_adjr[q] + (1.f - g) * en;
        }
        d_wcsr[dc.y] = w;
        atomicAdd(&d_degw[dc.x], w);
    }
}

// f32x2 row-pair GEMM: 128 rows x 64 cols per block, 256 threads (8 warps x 8 row-pairs).
// X = xn (normalized); epilogue scales by rsqrt(degw[row]) and optionally hnorm[row]
// (h = xn * ||h||, so h@W = ||h|| * (xn@W)).
#define GX_SMEM (64 * 128 * 8 + 128 * 64 * 4)   // Xp 64KB + Ws 32KB = 96KB
__global__ void __launch_bounds__(256) gemm128x2_kernel(const float* __restrict__ X,
                                                        const float* __restrict__ Wg, int N,
                                                        int useNorm) {
    extern __shared__ char smc[];
    unsigned long long* Xp = (unsigned long long*)smc;        // [64 rp][128 k] (rowA_k, rowB_k)
    float* Ws = (float*)(smc + 64 * 128 * 8);                 // [128 k][64 c]
    int t = threadIdx.x, w = t >> 5, lane = t & 31;
    int ct0 = blockIdx.y * 64;
    int rowBase = blockIdx.x * 128;
    for (int i = t; i < 128 * 64; i += 256) {
        int k = i >> 6, c = i & 63;
        Ws[i] = Wg[k * 128 + ct0 + c];
    }
    for (int i = t; i < 64 * 128; i += 256) {
        int rp = i >> 7, k = i & 127;
        int rA = rowBase + 2 * rp, rB = rA + 1;
        float a = (rA < N) ? X[(size_t)rA * 128 + k] : 0.f;
        float b = (rB < N) ? X[(size_t)rB * 128 + k] : 0.f;
        Xp[i] = pack2(a, b);
    }
    __syncthreads();
    unsigned long long acc0[8], acc1[8];
#pragma unroll
    for (int i = 0; i < 8; i++) { acc0[i] = 0ull; acc1[i] = 0ull; }
    const unsigned long long* xb = Xp + (w * 8) * 128;
#pragma unroll 2
    for (int k = 0; k < 128; k += 2) {
        float w0a = Ws[k * 64 + lane];
        float w1a = Ws[k * 64 + lane + 32];
        float w0b = Ws[(k + 1) * 64 + lane];
        float w1b = Ws[(k + 1) * 64 + lane + 32];
        unsigned long long W0a = pack2(w0a, w0a);
        unsigned long long W1a = pack2(w1a, w1a);
        unsigned long long W0b = pack2(w0b, w0b);
        unsigned long long W1b = pack2(w1b, w1b);
#pragma unroll
        for (int rp = 0; rp < 8; rp++) {
            ulonglong2 xp = *(const ulonglong2*)(xb + rp * 128 + k);   // broadcast 16B
            acc0[rp] = ffma2(xp.x, W0a, acc0[rp]);
            acc1[rp] = ffma2(xp.x, W1a, acc1[rp]);
            acc0[rp] = ffma2(xp.y, W0b, acc0[rp]);
            acc1[rp] = ffma2(xp.y, W1b, acc1[rp]);
        }
    }
#pragma unroll
    for (int rp = 0; rp < 8; rp++) {
        int rA = rowBase + 2 * (w * 8 + rp), rB = rA + 1;
        float2 c0 = unpack2f(acc0[rp]);
        float2 c1 = unpack2f(acc1[rp]);
        if (rA < N) {
            float dw = d_degw[rA];
            float sc = (dw > 0.f) ? rsqrtf(dw) : 0.f;
            if (useNorm) sc *= d_hnorm[rA];
            d_hw[(size_t)rA * 128 + ct0 + lane]      = c0.x * sc;
            d_hw[(size_t)rA * 128 + ct0 + lane + 32] = c1.x * sc;
        }
        if (rB < N) {
            float dw = d_degw[rB];
            float sc = (dw > 0.f) ? rsqrtf(dw) : 0.f;
            if (useNorm) sc *= d_hnorm[rB];
            d_hw[(size_t)rB * 128 + ct0 + lane]      = c0.y * sc;
            d_hw[(size_t)rB * 128 + ct0 + lane + 32] = c1.y * sc;
        }
    }
}

// layer-2 GEMM (FOUT=40), scalar; reads xn + hnorm scaling
template <int FOUT, int CT>
__global__ void __launch_bounds__(256) gemm_kernel(const float* __restrict__ X,
                                                   const float* __restrict__ Wg, int N,
                                                   int useNorm) {
    __shared__ float Ws[128 * CT];
    __shared__ float Xs[8][4][128];
    int t = threadIdx.x, w = t >> 5, lane = t & 31;
    int ct0 = blockIdx.y * CT;
    for (int i = t; i < 128 * CT; i += 256) {
        int k = i / CT, c = i - k * CT;
        Ws[i] = Wg[k * FOUT + ct0 + c];
    }
    int rowBase = blockIdx.x * 32 + w * 4;
#pragma unroll
    for (int r = 0; r < 4; r++) {
        int row = rowBase + r;
        float4 v = make_float4(0.f, 0.f, 0.f, 0.f);
        if (row < N) v = ((const float4*)(X + (size_t)row * 128))[lane];
        *(float4*)&Xs[w][r][lane * 4] = v;
    }
    __syncthreads();
    const bool has1 = (lane + 32) < CT;
    float a0[4] = {0.f, 0.f, 0.f, 0.f};
    float a1[4] = {0.f, 0.f, 0.f, 0.f};
#pragma unroll 4
    for (int k0 = 0; k0 < 128; k0 += 4) {
        float4 xv[4];
#pragma unroll
        for (int r = 0; r < 4; r++) xv[r] = *(const float4*)&Xs[w][r][k0];
#pragma unroll
        for (int kk = 0; kk < 4; kk++) {
            float w0 = Ws[(k0 + kk) * CT + lane];
            float w1 = has1 ? Ws[(k0 + kk) * CT + lane + 32] : 0.f;
#pragma unroll
            for (int r = 0; r < 4; r++) {
                float xs = (kk == 0) ? xv[r].x : (kk == 1) ? xv[r].y : (kk == 2) ? xv[r].z : xv[r].w;
                a0[r] = fmaf(xs, w0, a0[r]);
                a1[r] = fmaf(xs, w1, a1[r]);
            }
        }
    }
#pragma unroll
    for (int r = 0; r < 4; r++) {
        int row = rowBase + r;
        if (row < N) {
            float dw = d_degw[row];
            float sc = (dw > 0.f) ? rsqrtf(dw) : 0.f;
            if (useNorm) sc *= d_hnorm[row];
            d_hw[(size_t)row * FOUT + ct0 + lane] = a0[r] * sc;
            if (has1) d_hw[(size_t)row * FOUT + ct0 + lane + 32] = a1[r] * sc;
        }
    }
}

// Fused aggregation + relu; stores ONLY xn + hnorm (h never materialized) + degw re-zero.
__global__ void gather128_norm_kernel(const float* __restrict__ bias, int N) {
    int gid = blockIdx.x * blockDim.x + threadIdx.x;
    int node = gid >> 5;
    if (node >= N) return;
    int lane = gid & 31;
    int p0 = d_start2[(NMAX + 1) + node], p1 = d_start2[(NMAX + 1) + node + 1];
    float dw = d_degw[node];
    float dc = (dw > 0.f) ? rsqrtf(dw) : 0.f;
    float4 acc = make_float4(0.f, 0.f, 0.f, 0.f);
    int p = p0;
    for (; p + 3 < p1; p += 4) {
        int r0 = d_ccsr_src[p],     r1 = d_ccsr_src[p + 1];
        int r2 = d_ccsr_src[p + 2], r3 = d_ccsr_src[p + 3];
        float w0 = d_wcsr[p],     w1 = d_wcsr[p + 1];
        float w2 = d_wcsr[p + 2], w3 = d_wcsr[p + 3];
        float4 h0 = ((const float4*)(d_hw + (size_t)r0 * 128))[lane];
        float4 h1 = ((const float4*)(d_hw + (size_t)r1 * 128))[lane];
        float4 h2 = ((const float4*)(d_hw + (size_t)r2 * 128))[lane];
        float4 h3 = ((const float4*)(d_hw + (size_t)r3 * 128))[lane];
        acc.x = fmaf(w0, h0.x, fmaf(w1, h1.x, fmaf(w2, h2.x, fmaf(w3, h3.x, acc.x))));
        acc.y = fmaf(w0, h0.y, fmaf(w1, h1.y, fmaf(w2, h2.y, fmaf(w3, h3.y, acc.y))));
        acc.z = fmaf(w0, h0.z, fmaf(w1, h1.z, fmaf(w2, h2.z, fmaf(w3, h3.z, acc.z))));
        acc.w = fmaf(w0, h0.w, fmaf(w1, h1.w, fmaf(w2, h2.w, fmaf(w3, h3.w, acc.w))));
    }
    for (; p < p1; p++) {
        int r0 = d_ccsr_src[p];
        float w0 = d_wcsr[p];
        float4 h0 = ((const float4*)(d_hw + (size_t)r0 * 128))[lane];
        acc.x = fmaf(w0, h0.x, acc.x);
        acc.y = fmaf(w0, h0.y, acc.y);
        acc.z = fmaf(w0, h0.z, acc.z);
        acc.w = fmaf(w0, h0.w, acc.w);
    }
    float4 bv = ((const float4*)bias)[lane];
    acc.x = fmaxf(fmaf(acc.x, dc, bv.x), 0.f);
    acc.y = fmaxf(fmaf(acc.y, dc, bv.y), 0.f);
    acc.z = fmaxf(fmaf(acc.z, dc, bv.z), 0.f);
    acc.w = fmaxf(fmaf(acc.w, dc, bv.w), 0.f);
    // h = acc (not stored); store xn = h/||h|| and hnorm = ||h||
    float ss = acc.x * acc.x + acc.y * acc.y + acc.z * acc.z + acc.w * acc.w;
    ss = warpSum(ss);
    float nrm = sqrtf(ss);
    float inv = 1.f / fmaxf(nrm, 1e-12f);
    float4 xv = make_float4(acc.x * inv, acc.y * inv, acc.z * inv, acc.w * inv);
    ((float4*)(d_xn + (size_t)node * F))[lane] = xv;
    if (lane == 0) {
        d_hnorm[node] = nrm;
        d_degw[node] = 0.f;
    }
}

// Final layer: 40-class gather + fused log_softmax (warp/node), 2 edges in flight
__global__ void gather40_lsm_kernel(const float* __restrict__ bias, float* __restrict__ out, int N) {
    int gid = blockIdx.x * blockDim.x + threadIdx.x;
    int node = gid >> 5;
    if (node >= N) return;
    int lane = gid & 31;
    int p0 = d_start2[(NMAX + 1) + node], p1 = d_start2[(NMAX + 1) + node + 1];
    float dw = d_degw[node];
    float dc = (dw > 0.f) ? rsqrtf(dw) : 0.f;
    bool has1 = lane < 8;
    float a0 = 0.f, a1 = 0.f;
    int p = p0;
    for (; p + 1 < p1; p += 2) {
        int rA = d_ccsr_src[p], rB = d_ccsr_src[p + 1];
        float wA = d_wcsr[p], wB = d_wcsr[p + 1];
        const float* hA = d_hw + (size_t)rA * 40;
        const float* hB = d_hw + (size_t)rB * 40;
        float vA0 = hA[lane], vB0 = hB[lane];
        float vA1 = has1 ? hA[lane + 32] : 0.f;
        float vB1 = has1 ? hB[lane + 32] : 0.f;
        a0 = fmaf(wA, vA0, fmaf(wB, vB0, a0));
        a1 = fmaf(wA, vA1, fmaf(wB, vB1, a1));
    }
    if (p < p1) {
        int rA = d_ccsr_src[p];
        float wA = d_wcsr[p];
        const float* hA = d_hw + (size_t)rA * 40;
        a0 = fmaf(wA, hA[lane], a0);
        if (has1) a1 = fmaf(wA, hA[lane + 32], a1);
    }
    a0 = fmaf(a0, dc, bias[lane]);
    float v1 = -INFINITY;
    if (has1) { a1 = fmaf(a1, dc, bias[lane + 32]); v1 = a1; }
    float m = warpMax(fmaxf(a0, v1));
    float s = expf(a0 - m) + (has1 ? expf(a1 - m) : 0.f);
    s = warpSum(s);
    float lse = m + logf(s);
    out[(size_t)node * 40 + lane] = a0 - lse;
    if (has1) out[(size_t)node * 40 + lane + 32] = a1 - lse;
}

// ---------------- driver ----------------
extern "C" void kernel_launch(void* const* d_in, const int* in_sizes, int n_in,
                              void* d_out, int out_size) {
    const float* x    = (const float*)d_in[0];
    const float* gate = (const float*)d_in[1];
    const float* W0   = (const float*)d_in[2];
    const float* b0   = (const float*)d_in[3];
    const float* W1   = (const float*)d_in[4];
    const float* b1   = (const float*)d_in[5];
    const float* W2   = (const float*)d_in[6];
    const float* b2   = (const float*)d_in[7];
    const int*   ei   = (const int*)d_in[8];

    int N = in_sizes[0] / F;
    int E = in_sizes[8] / 2;
    const int* erow = ei;
    const int* ecol = ei + E;
    float* out = (float*)d_out;

    void* xn_v = nullptr;
    cudaGetSymbolAddress(&xn_v, d_xn);
    const float* xnp = (const float*)xn_v;

    cudaFuncSetAttribute(gemm128x2_kernel, cudaFuncAttributeMaxDynamicSharedMemorySize, GX_SMEM);

    const int TB = 256;
    int blkN  = (N + TB - 1) / TB;
    int blkWN = ((N * 32) + TB - 1) / TB;
    int nchunks = (N + 1023) / 1024;
    int Ehalf = (E + 1) / 2;
    int blkEh = (Ehalf + TB - 1) / TB;

    // ---- build both CSRs; normalize overlapped with hist ----
    combo_hist_norm_kernel<<<blkEh + blkWN, TB>>>(erow, ecol, E, x, N, blkEh, Ehalf);
    scan1_kernel<<<dim3(nchunks, 2), 256>>>(N);
    scan3_kernel<<<dim3(blkN, 2), TB>>>(N, nchunks);
    scatter2_kernel<<<blkEh, TB>>>(erow, ecol, E, Ehalf);

    dim3 ggrid2((N + 127) / 128, 2);   // f32x2 gemm: 128 rows x 64 cols per block
    dim3 ggrid40((N + 31) / 32, 1);

    // ---- layer 0 (gemm reads raw x; no hnorm) ----
    simweight_kernel<<<blkWN, TB>>>(gate, 0, N);
    gemm128x2_kernel<<<ggrid2, 256, GX_SMEM>>>(x, W0, N, 0);
    gather128_norm_kernel<<<blkWN, TB>>>(b0, N);

    // ---- layer 1 (gemm reads xn, scales by hnorm) ----
    simweight_kernel<<<blkWN, TB>>>(gate, 1, N);
    gemm128x2_kernel<<<ggrid2, 256, GX_SMEM>>>(xnp, W1, N, 1);
    gather128_norm_kernel<<<blkWN, TB>>>(b1, N);

    // ---- layer 2 ----
    simweight_kernel<<<blkWN, TB>>>(gate, 2, N);
    gemm_kernel<40, 40><<<ggrid40, 256>>>(xnp, W2, N, 1);
    gather40_lsm_kernel<<<blkWN, TB>>>(b2, out, N);
}